// round 13
// baseline (speedup 1.0000x reference)
#include <cuda_runtime.h>

// Problem constants (fixed by the dataset)
#define NN 100000
#define EE 1600000

// Scratch: __device__ globals only, referenced ONLY from device code
// (host-side symbol use binds the ATS-dereferenceable host shadow -> R2 bug).
__device__ int   g_is64;
__device__ int   g_deg[NN];
__device__ int   g_off[NN];
__device__ int   g_cur[NN];
__device__ int   g_csr[EE];
__device__ int   g_bsum[1024];
__device__ float g_t1[NN * 32];
__device__ float g_a1[NN * 32];
__device__ float g_t2[NN * 48];
__device__ float g_a2[NN * 48];
__device__ float g_t3[NN * 16];

// Packed fp32x2 helpers (Blackwell FFMA2 — exact fp32, 2 FMAs/inst)
__device__ __forceinline__ unsigned long long fma2(
    unsigned long long a, unsigned long long b, unsigned long long c) {
    unsigned long long d;
    asm("fma.rn.f32x2 %0, %1, %2, %3;" : "=l"(d) : "l"(a), "l"(b), "l"(c));
    return d;
}
__device__ __forceinline__ unsigned long long add2(
    unsigned long long a, unsigned long long b) {
    unsigned long long d;
    asm("add.rn.f32x2 %0, %1, %2;" : "=l"(d) : "l"(a), "l"(b));
    return d;
}
__device__ __forceinline__ unsigned long long bcast2(float v) {
    unsigned long long d;
    asm("mov.b64 %0, {%1, %1};" : "=l"(d) : "f"(v));
    return d;
}

// ---------------------------------------------------------------------------
// CSR build (side stream, hidden behind node1)
// ---------------------------------------------------------------------------
__global__ __launch_bounds__(256) void k_init(const void* __restrict__ ei, int N) {
    int i = blockIdx.x * blockDim.x + threadIdx.x;
    if (i < N) g_deg[i] = 0;
    if (i == 0) {
        const long long* p = (const long long*)ei;
        int ok = 1;
        for (int q = 0; q < 64; q++) {
            long long v = p[q];
            if (v < 0 || v >= (long long)N) { ok = 0; break; }
        }
        g_is64 = ok;
    }
}

__global__ __launch_bounds__(256) void k_hist(const void* __restrict__ ei, int E) {
    int i = blockIdx.x * blockDim.x + threadIdx.x;
    if (i >= E) return;
    int d;
    if (g_is64) d = (int)((const long long*)ei)[E + i];
    else        d = ((const int*)ei)[E + i];
    atomicAdd(&g_deg[d], 1);
}

__global__ __launch_bounds__(256) void k_scanA(int N) {
    __shared__ int s[256];
    int b = blockIdx.x, t = threadIdx.x;
    int base = b * 1024 + t * 4;
    int sum = 0;
#pragma unroll
    for (int i = 0; i < 4; i++) {
        int idx = base + i;
        if (idx < N) sum += g_deg[idx];
    }
    s[t] = sum;
    __syncthreads();
#pragma unroll
    for (int d = 128; d > 0; d >>= 1) {
        if (t < d) s[t] += s[t + d];
        __syncthreads();
    }
    if (t == 0) g_bsum[b] = s[0];
}

__global__ __launch_bounds__(256) void k_scanC(int N, int NB) {
    __shared__ int sb_[128];
    __shared__ int s[256];
    int b = blockIdx.x, t = threadIdx.x;
    if (t < 128) sb_[t] = (t < NB) ? g_bsum[t] : 0;
    __syncthreads();
#pragma unroll
    for (int d = 1; d < 128; d <<= 1) {
        int x = (t >= d && t < 128) ? sb_[t - d] : 0;
        __syncthreads();
        if (t < 128) sb_[t] += x;
        __syncthreads();
    }
    int boff = (b == 0) ? 0 : sb_[b - 1];

    int base = b * 1024 + t * 4;
    int v[4];
    int sum = 0;
#pragma unroll
    for (int i = 0; i < 4; i++) {
        int idx = base + i;
        v[i] = (idx < N) ? g_deg[idx] : 0;
        sum += v[i];
    }
    s[t] = sum;
    __syncthreads();
    for (int d = 1; d < 256; d <<= 1) {
        int x = (t >= d) ? s[t - d] : 0;
        __syncthreads();
        s[t] += x;
        __syncthreads();
    }
    int run = s[t] - sum + boff;
#pragma unroll
    for (int i = 0; i < 4; i++) {
        int idx = base + i;
        if (idx < N) {
            g_off[idx] = run;
            g_cur[idx] = run;
            run += v[i];
        }
    }
}

__global__ __launch_bounds__(256) void k_scatter(const void* __restrict__ ei, int E) {
    int i = blockIdx.x * blockDim.x + threadIdx.x;
    if (i >= E) return;
    int s, d;
    if (g_is64) {
        const long long* p = (const long long*)ei;
        s = (int)p[i];
        d = (int)p[E + i];
    } else {
        const int* p = (const int*)ei;
        s = p[i];
        d = p[E + i];
    }
    int pos = atomicAdd(&g_cur[d], 1);
    g_csr[pos] = s;
}

// ---------------------------------------------------------------------------
// Dual-GEMM j-tile body, FFMA2 (weights/bias from smem pointers sWr/sWo/sb)
// ---------------------------------------------------------------------------
#define JTILE_BODY2(IN, OUT)                                                   \
    unsigned long long at2[4], ar2[4];                                         \
    {                                                                          \
        ulonglong2 binit0 = *(const ulonglong2*)&sb[jt];                       \
        ulonglong2 binit1 = *(const ulonglong2*)&sb[jt + 4];                   \
        at2[0] = 0ull; at2[1] = 0ull; at2[2] = 0ull; at2[3] = 0ull;            \
        ar2[0] = binit0.x; ar2[1] = binit0.y;                                  \
        ar2[2] = binit1.x; ar2[3] = binit1.y;                                  \
    }                                                                          \
    _Pragma("unroll")                                                          \
    for (int k = 0; k < IN; k++) {                                             \
        unsigned long long hk2 = bcast2(h[k]);                                 \
        ulonglong2 wr01 = *(const ulonglong2*)&sWr[k * OUT + jt];              \
        ulonglong2 wr23 = *(const ulonglong2*)&sWr[k * OUT + jt + 4];          \
        ulonglong2 wo01 = *(const ulonglong2*)&sWo[k * OUT + jt];              \
        ulonglong2 wo23 = *(const ulonglong2*)&sWo[k * OUT + jt + 4];          \
        at2[0] = fma2(hk2, wr01.x, at2[0]);                                    \
        at2[1] = fma2(hk2, wr01.y, at2[1]);                                    \
        at2[2] = fma2(hk2, wr23.x, at2[2]);                                    \
        at2[3] = fma2(hk2, wr23.y, at2[3]);                                    \
        ar2[0] = fma2(hk2, wo01.x, ar2[0]);                                    \
        ar2[1] = fma2(hk2, wo01.y, ar2[1]);                                    \
        ar2[2] = fma2(hk2, wo23.x, ar2[2]);                                    \
        ar2[3] = fma2(hk2, wo23.y, ar2[3]);                                    \
    }

// Coalesced neighbor-row aggregation for one (node n, chunk c) task:
// accumulates float4 at column offset c*4 of each neighbor row (ROWF floats).
template <int ROWF>
__device__ __forceinline__ float4 agg_task(
    const float* __restrict__ t, int n, int c, float4 a)
{
    int beg = g_off[n];
    int end = beg + g_deg[n];
    float4 a2 = make_float4(0.f, 0.f, 0.f, 0.f);
    int j = beg;
    for (; j + 3 < end; j += 4) {
        int s0 = g_csr[j], s1 = g_csr[j+1], s2 = g_csr[j+2], s3 = g_csr[j+3];
        float4 v0 = *(const float4*)(t + (size_t)s0 * ROWF + c*4);
        float4 v1 = *(const float4*)(t + (size_t)s1 * ROWF + c*4);
        float4 v2 = *(const float4*)(t + (size_t)s2 * ROWF + c*4);
        float4 v3 = *(const float4*)(t + (size_t)s3 * ROWF + c*4);
        a.x += v0.x; a.y += v0.y; a.z += v0.z; a.w += v0.w;
        a2.x += v1.x; a2.y += v1.y; a2.z += v1.z; a2.w += v1.w;
        a.x += v2.x; a.y += v2.y; a.z += v2.z; a.w += v2.w;
        a2.x += v3.x; a2.y += v3.y; a2.z += v3.z; a2.w += v3.w;
    }
    for (; j < end; j++) {
        int s = g_csr[j];
        float4 v = *(const float4*)(t + (size_t)s * ROWF + c*4);
        a.x += v.x; a.y += v.y; a.z += v.z; a.w += v.w;
    }
    return make_float4(a.x + a2.x, a.y + a2.y, a.z + a2.z, a.w + a2.w);
}

// ---------------------------------------------------------------------------
// K1: layer 1 node kernel (unchanged). h0 = concat(x[48], ax[16]) -> 64
// ---------------------------------------------------------------------------
__global__ __launch_bounds__(256) void k_node1(
    const float* __restrict__ x, const float* __restrict__ ax,
    const float* __restrict__ Wrel, const float* __restrict__ Wroot,
    const float* __restrict__ b, int N)
{
    __shared__ __align__(16) float sWr[64 * 32];
    __shared__ __align__(16) float sWo[64 * 32];
    __shared__ __align__(16) float sb[32];
    for (int t = threadIdx.x; t < 64 * 32; t += 256) { sWr[t] = Wrel[t]; sWo[t] = Wroot[t]; }
    if (threadIdx.x < 32) sb[threadIdx.x] = b[threadIdx.x];
    __syncthreads();

    int i = blockIdx.x * 256 + threadIdx.x;
    if (i >= N) return;

    float h[64];
    const float4* xp = (const float4*)(x + (size_t)i * 48);
#pragma unroll
    for (int q = 0; q < 12; q++) {
        float4 v = xp[q];
        h[4*q] = v.x; h[4*q+1] = v.y; h[4*q+2] = v.z; h[4*q+3] = v.w;
    }
    const float4* ap = (const float4*)(ax + (size_t)i * 16);
#pragma unroll
    for (int q = 0; q < 4; q++) {
        float4 v = ap[q];
        h[48+4*q] = v.x; h[48+4*q+1] = v.y; h[48+4*q+2] = v.z; h[48+4*q+3] = v.w;
    }

    float* t1 = g_t1 + (size_t)i * 32;
    float* a1 = g_a1 + (size_t)i * 32;
#pragma unroll 1
    for (int jt = 0; jt < 32; jt += 8) {
        JTILE_BODY2(64, 32)
        *(ulonglong2*)&t1[jt]     = make_ulonglong2(at2[0], at2[1]);
        *(ulonglong2*)&t1[jt + 4] = make_ulonglong2(at2[2], at2[3]);
        *(ulonglong2*)&a1[jt]     = make_ulonglong2(ar2[0], ar2[1]);
        *(ulonglong2*)&a1[jt + 4] = make_ulonglong2(ar2[2], ar2[3]);
    }
}

// ---------------------------------------------------------------------------
// Fused layer 2: Phase A aggregates t1 (coalesced (node,chunk) tasks) into a
// transposed smem buffer hs[k][node] (stride 257 = conflict-free), Phase B
// runs the 48x48 dual GEMM with thread=node.
//   h1 = concat(relu(a1 + segsum t1), lf);  t2 = h1@W2rel; a2 = h1@W2root + b2
// smem floats: sWr 2304 | sWo 2304 | sb 64 | hs 48*257
// ---------------------------------------------------------------------------
#define HS_STRIDE 257
__global__ __launch_bounds__(256) void k_fused2(
    const float* __restrict__ lf,
    const float* __restrict__ Wrel, const float* __restrict__ Wroot,
    const float* __restrict__ b, int N)
{
    extern __shared__ __align__(16) float smem[];
    float* sWr = smem;
    float* sWo = smem + 2304;
    float* sb  = smem + 4608;
    float* hs  = smem + 4672;

    for (int t = threadIdx.x; t < 48 * 48; t += 256) { sWr[t] = Wrel[t]; sWo[t] = Wroot[t]; }
    if (threadIdx.x < 48) sb[threadIdx.x] = b[threadIdx.x];

    int base = blockIdx.x * 256;
    int nValid = N - base; if (nValid > 256) nValid = 256;

    // Phase A: aggregate rows of t1 (ROWF=32, CH=8) -> hs rows 0..31 (relu'd)
#pragma unroll 1
    for (int it = 0; it < 8; it++) {
        int idx = it * 256 + threadIdx.x;      // 0..2047
        int nl = idx >> 3;
        int c  = idx & 7;
        if (nl < nValid) {
            int n = base + nl;
            float4 a = *(const float4*)(g_a1 + (size_t)n * 32 + c * 4);
            a = agg_task<32>(g_t1, n, c, a);
            int k0 = c * 4;
            hs[(k0+0) * HS_STRIDE + nl] = fmaxf(a.x, 0.0f);
            hs[(k0+1) * HS_STRIDE + nl] = fmaxf(a.y, 0.0f);
            hs[(k0+2) * HS_STRIDE + nl] = fmaxf(a.z, 0.0f);
            hs[(k0+3) * HS_STRIDE + nl] = fmaxf(a.w, 0.0f);
        }
    }
    // lf concat -> hs rows 32..47
#pragma unroll 1
    for (int it = 0; it < 4; it++) {
        int idx = it * 256 + threadIdx.x;      // 0..1023
        int nl = idx >> 2;
        int c2 = idx & 3;
        if (nl < nValid) {
            float4 v = *(const float4*)(lf + (size_t)(base + nl) * 16 + c2 * 4);
            int k0 = 32 + c2 * 4;
            hs[(k0+0) * HS_STRIDE + nl] = v.x;
            hs[(k0+1) * HS_STRIDE + nl] = v.y;
            hs[(k0+2) * HS_STRIDE + nl] = v.z;
            hs[(k0+3) * HS_STRIDE + nl] = v.w;
        }
    }
    __syncthreads();

    // Phase B: dual GEMM, thread = node
    if (threadIdx.x >= nValid) return;
    int i = base + threadIdx.x;

    float h[48];
#pragma unroll
    for (int k = 0; k < 48; k++) h[k] = hs[k * HS_STRIDE + threadIdx.x];

    float* t2 = g_t2 + (size_t)i * 48;
    float* a2 = g_a2 + (size_t)i * 48;
#pragma unroll 1
    for (int jt = 0; jt < 48; jt += 8) {
        JTILE_BODY2(48, 48)
        *(ulonglong2*)&t2[jt]     = make_ulonglong2(at2[0], at2[1]);
        *(ulonglong2*)&t2[jt + 4] = make_ulonglong2(at2[2], at2[3]);
        *(ulonglong2*)&a2[jt]     = make_ulonglong2(ar2[0], ar2[1]);
        *(ulonglong2*)&a2[jt + 4] = make_ulonglong2(ar2[2], ar2[3]);
    }
}

// ---------------------------------------------------------------------------
// Fused layer 3: Phase A aggregates t2 (ROWF=48, CH=12) + a2 -> relu -> hs,
// Phase B dual GEMM 48->16: t3 = h2@W3rel ; out_init = h2@W3root + b3 + ax
// smem floats: sWr 768 | sWo 768 | sb 64 | hs 48*257
// ---------------------------------------------------------------------------
__global__ __launch_bounds__(256) void k_fused3(
    const float* __restrict__ ax,
    const float* __restrict__ Wrel, const float* __restrict__ Wroot,
    const float* __restrict__ b, float* __restrict__ out, int N)
{
    extern __shared__ __align__(16) float smem[];
    float* sWr = smem;
    float* sWo = smem + 768;
    float* sb  = smem + 1536;
    float* hs  = smem + 1600;

    for (int t = threadIdx.x; t < 48 * 16; t += 256) { sWr[t] = Wrel[t]; sWo[t] = Wroot[t]; }
    if (threadIdx.x < 16) sb[threadIdx.x] = b[threadIdx.x];

    int base = blockIdx.x * 256;
    int nValid = N - base; if (nValid > 256) nValid = 256;

    // Phase A: aggregate rows of t2 (ROWF=48, CH=12) -> hs rows 0..47 (relu'd)
#pragma unroll 1
    for (int it = 0; it < 12; it++) {
        int idx = it * 256 + threadIdx.x;      // 0..3071
        int nl = idx / 12;
        int c  = idx - nl * 12;
        if (nl < nValid) {
            int n = base + nl;
            float4 a = *(const float4*)(g_a2 + (size_t)n * 48 + c * 4);
            a = agg_task<48>(g_t2, n, c, a);
            int k0 = c * 4;
            hs[(k0+0) * HS_STRIDE + nl] = fmaxf(a.x, 0.0f);
            hs[(k0+1) * HS_STRIDE + nl] = fmaxf(a.y, 0.0f);
            hs[(k0+2) * HS_STRIDE + nl] = fmaxf(a.z, 0.0f);
            hs[(k0+3) * HS_STRIDE + nl] = fmaxf(a.w, 0.0f);
        }
    }
    __syncthreads();

    // Phase B: dual GEMM, thread = node
    if (threadIdx.x >= nValid) return;
    int i = base + threadIdx.x;

    float h[48];
#pragma unroll
    for (int k = 0; k < 48; k++) h[k] = hs[k * HS_STRIDE + threadIdx.x];

    const ulonglong2* axp = (const ulonglong2*)(ax + (size_t)i * 16);
    float* t3 = g_t3 + (size_t)i * 16;
    float* o  = out + (size_t)i * 16;
#pragma unroll 1
    for (int jt = 0; jt < 16; jt += 8) {
        JTILE_BODY2(48, 16)
        ulonglong2 av0 = axp[jt / 4];
        ulonglong2 av1 = axp[jt / 4 + 1];
        *(ulonglong2*)&t3[jt]     = make_ulonglong2(at2[0], at2[1]);
        *(ulonglong2*)&t3[jt + 4] = make_ulonglong2(at2[2], at2[3]);
        *(ulonglong2*)&o[jt]      = make_ulonglong2(add2(ar2[0], av0.x),
                                                    add2(ar2[1], av0.y));
        *(ulonglong2*)&o[jt + 4]  = make_ulonglong2(add2(ar2[2], av1.x),
                                                    add2(ar2[3], av1.y));
    }
}

// ---------------------------------------------------------------------------
// Final aggregation: out[i] += segsum of t3 rows (CH=4 lanes/node)
// ---------------------------------------------------------------------------
__global__ __launch_bounds__(256) void k_agg3(float* __restrict__ out, int N) {
    int tid = blockIdx.x * blockDim.x + threadIdx.x;
    if (tid >= N * 4) return;
    int n = tid >> 2;
    int c = tid & 3;

    float4 a = agg_task<16>(g_t3, n, c, make_float4(0.f, 0.f, 0.f, 0.f));

    float* ap = out + (size_t)n * 16 + c * 4;
    float4 cur = *(float4*)ap;
    *(float4*)ap = make_float4(cur.x + a.x, cur.y + a.y, cur.z + a.z, cur.w + a.w);
}

// ---------------------------------------------------------------------------
// kernel_launch: CSR ‖ node1 -> fused2 -> fused3 -> agg3
// ---------------------------------------------------------------------------
extern "C" void kernel_launch(void* const* d_in, const int* in_sizes, int n_in,
                              void* d_out, int out_size)
{
    const float* x   = (const float*)d_in[0];
    const void*  ei  = d_in[1];
    const float* ax  = (const float*)d_in[2];
    const float* lf  = (const float*)d_in[3];
    const float* W1r = (const float*)d_in[4];
    const float* b1  = (const float*)d_in[5];
    const float* W1o = (const float*)d_in[6];
    const float* W2r = (const float*)d_in[7];
    const float* b2  = (const float*)d_in[8];
    const float* W2o = (const float*)d_in[9];
    const float* W3r = (const float*)d_in[10];
    const float* b3  = (const float*)d_in[11];
    const float* W3o = (const float*)d_in[12];
    float* out = (float*)d_out;

    const int N = in_sizes[0] / 48;
    const int E = in_sizes[1] / 2;

    const int TB = 256;
    const int nodeBlocks = (N + TB - 1) / TB;
    const int edgeBlocks = (E + TB - 1) / TB;
    const int NB = (N + 1023) / 1024;

    const int SMEM2 = (4672 + 48 * HS_STRIDE) * 4;   // 68032 B
    const int SMEM3 = (1600 + 48 * HS_STRIDE) * 4;   // 55744 B

    static cudaStream_t s2 = nullptr;
    static cudaEvent_t evFork = nullptr, evJoin = nullptr;
    if (!s2) {
        cudaStreamCreateWithFlags(&s2, cudaStreamNonBlocking);
        cudaEventCreateWithFlags(&evFork, cudaEventDisableTiming);
        cudaEventCreateWithFlags(&evJoin, cudaEventDisableTiming);
        cudaFuncSetAttribute(k_fused2, cudaFuncAttributeMaxDynamicSharedMemorySize, SMEM2);
        cudaFuncSetAttribute(k_fused3, cudaFuncAttributeMaxDynamicSharedMemorySize, SMEM3);
    }

    // Fork: CSR build on s2, node1 on the main (capture) stream.
    cudaEventRecord(evFork, 0);
    cudaStreamWaitEvent(s2, evFork, 0);

    k_init   <<<nodeBlocks, TB, 0, s2>>>(ei, N);
    k_hist   <<<edgeBlocks, TB, 0, s2>>>(ei, E);
    k_scanA  <<<NB, TB, 0, s2>>>(N);
    k_scanC  <<<NB, TB, 0, s2>>>(N, NB);
    k_scatter<<<edgeBlocks, TB, 0, s2>>>(ei, E);
    cudaEventRecord(evJoin, s2);

    // Layer 1 transform runs concurrently with the CSR build.
    k_node1<<<nodeBlocks, TB>>>(x, ax, W1r, W1o, b1, N);

    // Join, then fused layers.
    cudaStreamWaitEvent(0, evJoin, 0);
    k_fused2<<<nodeBlocks, TB, SMEM2>>>(lf, W2r, W2o, b2, N);
    k_fused3<<<nodeBlocks, TB, SMEM3>>>(ax, W3r, W3o, b3, out, N);
    k_agg3<<<((long long)N * 4 + TB - 1) / TB, TB>>>(out, N);
}

// round 14
// speedup vs baseline: 1.0706x; 1.0706x over previous
#include <cuda_runtime.h>

// Problem constants (fixed by the dataset)
#define NN 100000
#define EE 1600000

// Scratch: __device__ globals only, referenced ONLY from device code
// (host-side symbol use binds the ATS-dereferenceable host shadow -> R2 bug).
__device__ int   g_is64;
__device__ int   g_deg[NN];
__device__ int   g_off[NN];
__device__ int   g_cur[NN];
__device__ int   g_csr[EE];
__device__ int   g_bsum[1024];
__device__ float g_t1[NN * 32];
__device__ float g_a1[NN * 32];
__device__ float g_t2[NN * 48];
__device__ float g_a2[NN * 48];
__device__ float g_t3[NN * 16];

// Packed fp32x2 helpers (Blackwell FFMA2 — exact fp32, 2 FMAs/inst)
__device__ __forceinline__ unsigned long long fma2(
    unsigned long long a, unsigned long long b, unsigned long long c) {
    unsigned long long d;
    asm("fma.rn.f32x2 %0, %1, %2, %3;" : "=l"(d) : "l"(a), "l"(b), "l"(c));
    return d;
}
__device__ __forceinline__ unsigned long long add2(
    unsigned long long a, unsigned long long b) {
    unsigned long long d;
    asm("add.rn.f32x2 %0, %1, %2;" : "=l"(d) : "l"(a), "l"(b));
    return d;
}
__device__ __forceinline__ unsigned long long bcast2(float v) {
    unsigned long long d;
    asm("mov.b64 %0, {%1, %1};" : "=l"(d) : "f"(v));
    return d;
}

// ---------------------------------------------------------------------------
// CSR build (side stream, hidden behind node1)
// ---------------------------------------------------------------------------
__global__ __launch_bounds__(256) void k_init(const void* __restrict__ ei, int N) {
    int i = blockIdx.x * blockDim.x + threadIdx.x;
    if (i < N) g_deg[i] = 0;
    if (i == 0) {
        const long long* p = (const long long*)ei;
        int ok = 1;
        for (int q = 0; q < 64; q++) {
            long long v = p[q];
            if (v < 0 || v >= (long long)N) { ok = 0; break; }
        }
        g_is64 = ok;
    }
}

__global__ __launch_bounds__(256) void k_hist(const void* __restrict__ ei, int E) {
    int i = blockIdx.x * blockDim.x + threadIdx.x;
    if (i >= E) return;
    int d;
    if (g_is64) d = (int)((const long long*)ei)[E + i];
    else        d = ((const int*)ei)[E + i];
    atomicAdd(&g_deg[d], 1);
}

__global__ __launch_bounds__(256) void k_scanA(int N) {
    __shared__ int s[256];
    int b = blockIdx.x, t = threadIdx.x;
    int base = b * 1024 + t * 4;
    int sum = 0;
#pragma unroll
    for (int i = 0; i < 4; i++) {
        int idx = base + i;
        if (idx < N) sum += g_deg[idx];
    }
    s[t] = sum;
    __syncthreads();
#pragma unroll
    for (int d = 128; d > 0; d >>= 1) {
        if (t < d) s[t] += s[t + d];
        __syncthreads();
    }
    if (t == 0) g_bsum[b] = s[0];
}

__global__ __launch_bounds__(256) void k_scanC(int N, int NB) {
    __shared__ int sb_[128];
    __shared__ int s[256];
    int b = blockIdx.x, t = threadIdx.x;
    if (t < 128) sb_[t] = (t < NB) ? g_bsum[t] : 0;
    __syncthreads();
#pragma unroll
    for (int d = 1; d < 128; d <<= 1) {
        int x = (t >= d && t < 128) ? sb_[t - d] : 0;
        __syncthreads();
        if (t < 128) sb_[t] += x;
        __syncthreads();
    }
    int boff = (b == 0) ? 0 : sb_[b - 1];

    int base = b * 1024 + t * 4;
    int v[4];
    int sum = 0;
#pragma unroll
    for (int i = 0; i < 4; i++) {
        int idx = base + i;
        v[i] = (idx < N) ? g_deg[idx] : 0;
        sum += v[i];
    }
    s[t] = sum;
    __syncthreads();
    for (int d = 1; d < 256; d <<= 1) {
        int x = (t >= d) ? s[t - d] : 0;
        __syncthreads();
        s[t] += x;
        __syncthreads();
    }
    int run = s[t] - sum + boff;
#pragma unroll
    for (int i = 0; i < 4; i++) {
        int idx = base + i;
        if (idx < N) {
            g_off[idx] = run;
            g_cur[idx] = run;
            run += v[i];
        }
    }
}

__global__ __launch_bounds__(256) void k_scatter(const void* __restrict__ ei, int E) {
    int i = blockIdx.x * blockDim.x + threadIdx.x;
    if (i >= E) return;
    int s, d;
    if (g_is64) {
        const long long* p = (const long long*)ei;
        s = (int)p[i];
        d = (int)p[E + i];
    } else {
        const int* p = (const int*)ei;
        s = p[i];
        d = p[E + i];
    }
    int pos = atomicAdd(&g_cur[d], 1);
    g_csr[pos] = s;
}

// ---------------------------------------------------------------------------
// Single-node dual-GEMM j-tile body (FFMA2), weights from smem.
// ---------------------------------------------------------------------------
#define JTILE_BODY2(IN, OUT)                                                   \
    unsigned long long at2[4], ar2[4];                                         \
    {                                                                          \
        ulonglong2 binit0 = *(const ulonglong2*)&sb[jt];                       \
        ulonglong2 binit1 = *(const ulonglong2*)&sb[jt + 4];                   \
        at2[0] = 0ull; at2[1] = 0ull; at2[2] = 0ull; at2[3] = 0ull;            \
        ar2[0] = binit0.x; ar2[1] = binit0.y;                                  \
        ar2[2] = binit1.x; ar2[3] = binit1.y;                                  \
    }                                                                          \
    _Pragma("unroll")                                                          \
    for (int k = 0; k < IN; k++) {                                             \
        unsigned long long hk2 = bcast2(h[k]);                                 \
        ulonglong2 wr01 = *(const ulonglong2*)&sWr[k * OUT + jt];              \
        ulonglong2 wr23 = *(const ulonglong2*)&sWr[k * OUT + jt + 4];          \
        ulonglong2 wo01 = *(const ulonglong2*)&sWo[k * OUT + jt];              \
        ulonglong2 wo23 = *(const ulonglong2*)&sWo[k * OUT + jt + 4];          \
        at2[0] = fma2(hk2, wr01.x, at2[0]);                                    \
        at2[1] = fma2(hk2, wr01.y, at2[1]);                                    \
        at2[2] = fma2(hk2, wr23.x, at2[2]);                                    \
        at2[3] = fma2(hk2, wr23.y, at2[3]);                                    \
        ar2[0] = fma2(hk2, wo01.x, ar2[0]);                                    \
        ar2[1] = fma2(hk2, wo01.y, ar2[1]);                                    \
        ar2[2] = fma2(hk2, wo23.x, ar2[2]);                                    \
        ar2[3] = fma2(hk2, wo23.y, ar2[3]);                                    \
    }

// Two-node variant: weight LDS shared across both nodes (halves LDS/node).
#define JTILE_BODY2X2(IN, OUT)                                                 \
    unsigned long long at2a[4], ar2a[4], at2b[4], ar2b[4];                     \
    {                                                                          \
        ulonglong2 binit0 = *(const ulonglong2*)&sb[jt];                       \
        ulonglong2 binit1 = *(const ulonglong2*)&sb[jt + 4];                   \
        at2a[0]=0ull; at2a[1]=0ull; at2a[2]=0ull; at2a[3]=0ull;                \
        at2b[0]=0ull; at2b[1]=0ull; at2b[2]=0ull; at2b[3]=0ull;                \
        ar2a[0]=binit0.x; ar2a[1]=binit0.y; ar2a[2]=binit1.x; ar2a[3]=binit1.y;\
        ar2b[0]=binit0.x; ar2b[1]=binit0.y; ar2b[2]=binit1.x; ar2b[3]=binit1.y;\
    }                                                                          \
    _Pragma("unroll")                                                          \
    for (int k = 0; k < IN; k++) {                                             \
        unsigned long long hka = bcast2(h0[k]);                                \
        unsigned long long hkb = bcast2(h1[k]);                                \
        ulonglong2 wr01 = *(const ulonglong2*)&sWr[k * OUT + jt];              \
        ulonglong2 wr23 = *(const ulonglong2*)&sWr[k * OUT + jt + 4];          \
        ulonglong2 wo01 = *(const ulonglong2*)&sWo[k * OUT + jt];              \
        ulonglong2 wo23 = *(const ulonglong2*)&sWo[k * OUT + jt + 4];          \
        at2a[0]=fma2(hka, wr01.x, at2a[0]); at2b[0]=fma2(hkb, wr01.x, at2b[0]);\
        at2a[1]=fma2(hka, wr01.y, at2a[1]); at2b[1]=fma2(hkb, wr01.y, at2b[1]);\
        at2a[2]=fma2(hka, wr23.x, at2a[2]); at2b[2]=fma2(hkb, wr23.x, at2b[2]);\
        at2a[3]=fma2(hka, wr23.y, at2a[3]); at2b[3]=fma2(hkb, wr23.y, at2b[3]);\
        ar2a[0]=fma2(hka, wo01.x, ar2a[0]); ar2b[0]=fma2(hkb, wo01.x, ar2b[0]);\
        ar2a[1]=fma2(hka, wo01.y, ar2a[1]); ar2b[1]=fma2(hkb, wo01.y, ar2b[1]);\
        ar2a[2]=fma2(hka, wo23.x, ar2a[2]); ar2b[2]=fma2(hkb, wo23.x, ar2b[2]);\
        ar2a[3]=fma2(hka, wo23.y, ar2a[3]); ar2b[3]=fma2(hkb, wo23.y, ar2b[3]);\
    }

// ---------------------------------------------------------------------------
// K1: layer 1 node kernel (single-node; overlapped with CSR build anyway)
// ---------------------------------------------------------------------------
__global__ __launch_bounds__(256) void k_node1(
    const float* __restrict__ x, const float* __restrict__ ax,
    const float* __restrict__ Wrel, const float* __restrict__ Wroot,
    const float* __restrict__ b, int N)
{
    __shared__ __align__(16) float sWr[64 * 32];
    __shared__ __align__(16) float sWo[64 * 32];
    __shared__ __align__(16) float sb[32];
    for (int t = threadIdx.x; t < 64 * 32; t += 256) { sWr[t] = Wrel[t]; sWo[t] = Wroot[t]; }
    if (threadIdx.x < 32) sb[threadIdx.x] = b[threadIdx.x];
    __syncthreads();

    int i = blockIdx.x * 256 + threadIdx.x;
    if (i >= N) return;

    float h[64];
    const float4* xp = (const float4*)(x + (size_t)i * 48);
#pragma unroll
    for (int q = 0; q < 12; q++) {
        float4 v = xp[q];
        h[4*q] = v.x; h[4*q+1] = v.y; h[4*q+2] = v.z; h[4*q+3] = v.w;
    }
    const float4* ap = (const float4*)(ax + (size_t)i * 16);
#pragma unroll
    for (int q = 0; q < 4; q++) {
        float4 v = ap[q];
        h[48+4*q] = v.x; h[48+4*q+1] = v.y; h[48+4*q+2] = v.z; h[48+4*q+3] = v.w;
    }

    float* t1 = g_t1 + (size_t)i * 32;
    float* a1 = g_a1 + (size_t)i * 32;
#pragma unroll 1
    for (int jt = 0; jt < 32; jt += 8) {
        JTILE_BODY2(64, 32)
        *(ulonglong2*)&t1[jt]     = make_ulonglong2(at2[0], at2[1]);
        *(ulonglong2*)&t1[jt + 4] = make_ulonglong2(at2[2], at2[3]);
        *(ulonglong2*)&a1[jt]     = make_ulonglong2(ar2[0], ar2[1]);
        *(ulonglong2*)&a1[jt + 4] = make_ulonglong2(ar2[2], ar2[3]);
    }
}

// ---------------------------------------------------------------------------
// K3: layer 2 node kernel, TWO nodes per thread (TB=128, 256 nodes/block)
// ---------------------------------------------------------------------------
__global__ __launch_bounds__(128) void k_node2(
    const float* __restrict__ lf,
    const float* __restrict__ Wrel, const float* __restrict__ Wroot,
    const float* __restrict__ b, int N)
{
    __shared__ __align__(16) float sWr[48 * 48];
    __shared__ __align__(16) float sWo[48 * 48];
    __shared__ __align__(16) float sb[48];
    for (int t = threadIdx.x; t < 48 * 48; t += 128) { sWr[t] = Wrel[t]; sWo[t] = Wroot[t]; }
    if (threadIdx.x < 48) sb[threadIdx.x] = b[threadIdx.x];
    __syncthreads();

    int i0 = blockIdx.x * 256 + threadIdx.x * 2;
    if (i0 >= N) return;
    bool has1 = (i0 + 1 < N);
    int i1 = has1 ? i0 + 1 : i0;

    float h0[48], h1[48];
    {
        const float4* a1p = (const float4*)(g_a1 + (size_t)i0 * 32);
        const float4* b1p = (const float4*)(g_a1 + (size_t)i1 * 32);
#pragma unroll
        for (int q = 0; q < 8; q++) {
            float4 v0 = a1p[q], v1 = b1p[q];
            h0[4*q]   = fmaxf(v0.x, 0.0f); h1[4*q]   = fmaxf(v1.x, 0.0f);
            h0[4*q+1] = fmaxf(v0.y, 0.0f); h1[4*q+1] = fmaxf(v1.y, 0.0f);
            h0[4*q+2] = fmaxf(v0.z, 0.0f); h1[4*q+2] = fmaxf(v1.z, 0.0f);
            h0[4*q+3] = fmaxf(v0.w, 0.0f); h1[4*q+3] = fmaxf(v1.w, 0.0f);
        }
        const float4* l0 = (const float4*)(lf + (size_t)i0 * 16);
        const float4* l1 = (const float4*)(lf + (size_t)i1 * 16);
#pragma unroll
        for (int q = 0; q < 4; q++) {
            float4 v0 = l0[q], v1 = l1[q];
            h0[32+4*q]   = v0.x; h1[32+4*q]   = v1.x;
            h0[32+4*q+1] = v0.y; h1[32+4*q+1] = v1.y;
            h0[32+4*q+2] = v0.z; h1[32+4*q+2] = v1.z;
            h0[32+4*q+3] = v0.w; h1[32+4*q+3] = v1.w;
        }
    }

    float* t2a = g_t2 + (size_t)i0 * 48;
    float* a2a = g_a2 + (size_t)i0 * 48;
    float* t2b = g_t2 + (size_t)i1 * 48;
    float* a2b = g_a2 + (size_t)i1 * 48;
#pragma unroll 1
    for (int jt = 0; jt < 48; jt += 8) {
        JTILE_BODY2X2(48, 48)
        *(ulonglong2*)&t2a[jt]     = make_ulonglong2(at2a[0], at2a[1]);
        *(ulonglong2*)&t2a[jt + 4] = make_ulonglong2(at2a[2], at2a[3]);
        *(ulonglong2*)&a2a[jt]     = make_ulonglong2(ar2a[0], ar2a[1]);
        *(ulonglong2*)&a2a[jt + 4] = make_ulonglong2(ar2a[2], ar2a[3]);
        if (has1) {
            *(ulonglong2*)&t2b[jt]     = make_ulonglong2(at2b[0], at2b[1]);
            *(ulonglong2*)&t2b[jt + 4] = make_ulonglong2(at2b[2], at2b[3]);
            *(ulonglong2*)&a2b[jt]     = make_ulonglong2(ar2b[0], ar2b[1]);
            *(ulonglong2*)&a2b[jt + 4] = make_ulonglong2(ar2b[2], ar2b[3]);
        }
    }
}

// ---------------------------------------------------------------------------
// K5: layer 3 node kernel, TWO nodes per thread (TB=128, 256 nodes/block)
// ---------------------------------------------------------------------------
__global__ __launch_bounds__(128) void k_node3(
    const float* __restrict__ ax,
    const float* __restrict__ Wrel, const float* __restrict__ Wroot,
    const float* __restrict__ b, float* __restrict__ out, int N)
{
    __shared__ __align__(16) float sWr[48 * 16];
    __shared__ __align__(16) float sWo[48 * 16];
    __shared__ __align__(16) float sb[16];
    for (int t = threadIdx.x; t < 48 * 16; t += 128) { sWr[t] = Wrel[t]; sWo[t] = Wroot[t]; }
    if (threadIdx.x < 16) sb[threadIdx.x] = b[threadIdx.x];
    __syncthreads();

    int i0 = blockIdx.x * 256 + threadIdx.x * 2;
    if (i0 >= N) return;
    bool has1 = (i0 + 1 < N);
    int i1 = has1 ? i0 + 1 : i0;

    float h0[48], h1[48];
    {
        const float4* a0p = (const float4*)(g_a2 + (size_t)i0 * 48);
        const float4* a1p = (const float4*)(g_a2 + (size_t)i1 * 48);
#pragma unroll
        for (int q = 0; q < 12; q++) {
            float4 v0 = a0p[q], v1 = a1p[q];
            h0[4*q]   = fmaxf(v0.x, 0.0f); h1[4*q]   = fmaxf(v1.x, 0.0f);
            h0[4*q+1] = fmaxf(v0.y, 0.0f); h1[4*q+1] = fmaxf(v1.y, 0.0f);
            h0[4*q+2] = fmaxf(v0.z, 0.0f); h1[4*q+2] = fmaxf(v1.z, 0.0f);
            h0[4*q+3] = fmaxf(v0.w, 0.0f); h1[4*q+3] = fmaxf(v1.w, 0.0f);
        }
    }

    const ulonglong2* ax0 = (const ulonglong2*)(ax + (size_t)i0 * 16);
    const ulonglong2* ax1 = (const ulonglong2*)(ax + (size_t)i1 * 16);
    float* t3a = g_t3 + (size_t)i0 * 16;
    float* t3b = g_t3 + (size_t)i1 * 16;
    float* oa  = out + (size_t)i0 * 16;
    float* ob  = out + (size_t)i1 * 16;
#pragma unroll 1
    for (int jt = 0; jt < 16; jt += 8) {
        JTILE_BODY2X2(48, 16)
        ulonglong2 av0 = ax0[jt / 4];
        ulonglong2 av1 = ax0[jt / 4 + 1];
        *(ulonglong2*)&t3a[jt]     = make_ulonglong2(at2a[0], at2a[1]);
        *(ulonglong2*)&t3a[jt + 4] = make_ulonglong2(at2a[2], at2a[3]);
        *(ulonglong2*)&oa[jt]      = make_ulonglong2(add2(ar2a[0], av0.x),
                                                     add2(ar2a[1], av0.y));
        *(ulonglong2*)&oa[jt + 4]  = make_ulonglong2(add2(ar2a[2], av1.x),
                                                     add2(ar2a[3], av1.y));
        if (has1) {
            ulonglong2 bv0 = ax1[jt / 4];
            ulonglong2 bv1 = ax1[jt / 4 + 1];
            *(ulonglong2*)&t3b[jt]     = make_ulonglong2(at2b[0], at2b[1]);
            *(ulonglong2*)&t3b[jt + 4] = make_ulonglong2(at2b[2], at2b[3]);
            *(ulonglong2*)&ob[jt]      = make_ulonglong2(add2(ar2b[0], bv0.x),
                                                         add2(ar2b[1], bv0.y));
            *(ulonglong2*)&ob[jt + 4]  = make_ulonglong2(add2(ar2b[2], bv1.x),
                                                         add2(ar2b[3], bv1.y));
        }
    }
}

// ---------------------------------------------------------------------------
// CSR aggregation: thread (node, chunk), unroll-8 neighbors for MLP.
// CH adjacent lanes cover one node's chunks -> coalesced 128B groups.
// ---------------------------------------------------------------------------
template <int CH>
__device__ __forceinline__ void agg_body(
    const float* __restrict__ t, float* __restrict__ acc, int N)
{
    int tid = blockIdx.x * blockDim.x + threadIdx.x;
    if (tid >= N * CH) return;
    int n = tid / CH;
    int c = tid - n * CH;

    int beg = g_off[n];
    int end = beg + g_deg[n];

    float4 a0 = make_float4(0.f,0.f,0.f,0.f);
    float4 a1 = make_float4(0.f,0.f,0.f,0.f);
    float4 a2 = make_float4(0.f,0.f,0.f,0.f);
    float4 a3 = make_float4(0.f,0.f,0.f,0.f);

    int j = beg;
    for (; j + 7 < end; j += 8) {
        int s0 = g_csr[j],   s1 = g_csr[j+1], s2 = g_csr[j+2], s3 = g_csr[j+3];
        int s4 = g_csr[j+4], s5 = g_csr[j+5], s6 = g_csr[j+6], s7 = g_csr[j+7];
        float4 v0 = *(const float4*)(t + (size_t)s0 * (CH*4) + c*4);
        float4 v1 = *(const float4*)(t + (size_t)s1 * (CH*4) + c*4);
        float4 v2 = *(const float4*)(t + (size_t)s2 * (CH*4) + c*4);
        float4 v3 = *(const float4*)(t + (size_t)s3 * (CH*4) + c*4);
        float4 v4 = *(const float4*)(t + (size_t)s4 * (CH*4) + c*4);
        float4 v5 = *(const float4*)(t + (size_t)s5 * (CH*4) + c*4);
        float4 v6 = *(const float4*)(t + (size_t)s6 * (CH*4) + c*4);
        float4 v7 = *(const float4*)(t + (size_t)s7 * (CH*4) + c*4);
        a0.x += v0.x + v4.x; a0.y += v0.y + v4.y; a0.z += v0.z + v4.z; a0.w += v0.w + v4.w;
        a1.x += v1.x + v5.x; a1.y += v1.y + v5.y; a1.z += v1.z + v5.z; a1.w += v1.w + v5.w;
        a2.x += v2.x + v6.x; a2.y += v2.y + v6.y; a2.z += v2.z + v6.z; a2.w += v2.w + v6.w;
        a3.x += v3.x + v7.x; a3.y += v3.y + v7.y; a3.z += v3.z + v7.z; a3.w += v3.w + v7.w;
    }
    for (; j + 1 < end; j += 2) {
        int s0 = g_csr[j], s1 = g_csr[j+1];
        float4 v0 = *(const float4*)(t + (size_t)s0 * (CH*4) + c*4);
        float4 v1 = *(const float4*)(t + (size_t)s1 * (CH*4) + c*4);
        a0.x += v0.x; a0.y += v0.y; a0.z += v0.z; a0.w += v0.w;
        a1.x += v1.x; a1.y += v1.y; a1.z += v1.z; a1.w += v1.w;
    }
    if (j < end) {
        int s = g_csr[j];
        float4 v = *(const float4*)(t + (size_t)s * (CH*4) + c*4);
        a0.x += v.x; a0.y += v.y; a0.z += v.z; a0.w += v.w;
    }

    float* ap = acc + (size_t)n * (CH*4) + c*4;
    float4 cur = *(float4*)ap;
    *(float4*)ap = make_float4(cur.x + a0.x + a1.x + a2.x + a3.x,
                               cur.y + a0.y + a1.y + a2.y + a3.y,
                               cur.z + a0.z + a1.z + a2.z + a3.z,
                               cur.w + a0.w + a1.w + a2.w + a3.w);
}

__global__ __launch_bounds__(256) void k_agg1(int N) { agg_body<8> (g_t1, g_a1, N); }
__global__ __launch_bounds__(256) void k_agg2(int N) { agg_body<12>(g_t2, g_a2, N); }
__global__ __launch_bounds__(256) void k_agg3(float* __restrict__ out, int N) {
    agg_body<4>(g_t3, out, N);
}

// ---------------------------------------------------------------------------
// kernel_launch: CSR ‖ node1 -> agg1 -> node2 -> agg2 -> node3 -> agg3
// ---------------------------------------------------------------------------
extern "C" void kernel_launch(void* const* d_in, const int* in_sizes, int n_in,
                              void* d_out, int out_size)
{
    const float* x   = (const float*)d_in[0];
    const void*  ei  = d_in[1];
    const float* ax  = (const float*)d_in[2];
    const float* lf  = (const float*)d_in[3];
    const float* W1r = (const float*)d_in[4];
    const float* b1  = (const float*)d_in[5];
    const float* W1o = (const float*)d_in[6];
    const float* W2r = (const float*)d_in[7];
    const float* b2  = (const float*)d_in[8];
    const float* W2o = (const float*)d_in[9];
    const float* W3r = (const float*)d_in[10];
    const float* b3  = (const float*)d_in[11];
    const float* W3o = (const float*)d_in[12];
    float* out = (float*)d_out;

    const int N = in_sizes[0] / 48;
    const int E = in_sizes[1] / 2;

    const int TB = 256;
    const int nodeBlocks  = (N + TB - 1) / TB;
    const int pairBlocks  = (N + 255) / 256;   // 2-node kernels: 128 thr, 256 nodes
    const int edgeBlocks  = (E + TB - 1) / TB;
    const int NB = (N + 1023) / 1024;

    static cudaStream_t s2 = nullptr;
    static cudaEvent_t evFork = nullptr, evJoin = nullptr;
    if (!s2) {
        cudaStreamCreateWithFlags(&s2, cudaStreamNonBlocking);
        cudaEventCreateWithFlags(&evFork, cudaEventDisableTiming);
        cudaEventCreateWithFlags(&evJoin, cudaEventDisableTiming);
    }

    // Fork: CSR build on s2, node1 on the main (capture) stream.
    cudaEventRecord(evFork, 0);
    cudaStreamWaitEvent(s2, evFork, 0);

    k_init   <<<nodeBlocks, TB, 0, s2>>>(ei, N);
    k_hist   <<<edgeBlocks, TB, 0, s2>>>(ei, E);
    k_scanA  <<<NB, TB, 0, s2>>>(N);
    k_scanC  <<<NB, TB, 0, s2>>>(N, NB);
    k_scatter<<<edgeBlocks, TB, 0, s2>>>(ei, E);
    cudaEventRecord(evJoin, s2);

    // Layer 1 transform runs concurrently with the CSR build.
    k_node1<<<nodeBlocks, TB>>>(x, ax, W1r, W1o, b1, N);

    // Join: aggregation needs both CSR and t1.
    cudaStreamWaitEvent(0, evJoin, 0);
    k_agg1<<<((long long)N * 8 + TB - 1) / TB, TB>>>(N);

    // Layer 2 (2 nodes/thread)
    k_node2<<<pairBlocks, 128>>>(lf, W2r, W2o, b2, N);
    k_agg2<<<((long long)N * 12 + TB - 1) / TB, TB>>>(N);

    // Layer 3 (2 nodes/thread), accumulate straight into d_out
    k_node3<<<pairBlocks, 128>>>(ax, W3r, W3o, b3, out, N);
    k_agg3<<<((long long)N * 4 + TB - 1) / TB, TB>>>(out, N);
}